// round 7
// baseline (speedup 1.0000x reference)
#include <cuda_runtime.h>
#include <math.h>

#define BB 64
#define TT 32
#define EE 300
#define HH 1024
#define VV 10000

#define E_PAD 320
#define NT1   ((E_PAD + HH) / 32)   // 42 k-tiles, layer 1
#define NTILE0_1 (E_PAD / 32)       // 10
#define NT2   ((HH + HH) / 32)      // 64 k-tiles, layer 2
#define NTILE0_2 (HH / 32)          // 32
#define NB 32                        // n-groups of 128 gate-cols

#define NSTAGE 8
#define A_TILE_WORDS (32 * 32)       // M=32 x K=32
#define W_TILE_WORDS (128 * 32)      // N=128 x K=32
#define STAGE_WORDS  (A_TILE_WORDS + W_TILE_WORDS)   // 5120
#define STAGE_BYTES  (STAGE_WORDS * 4)               // 20480
#define SMEM_DYN     (NSTAGE * STAGE_BYTES)          // 163840

// ---- persistent device scratch (no allocation allowed) ----
__device__ float g_w1pre[NB * NT1 * 128 * 32];   // pre-swizzled tf32 L1 weights
__device__ float g_w2pre[NB * NT2 * 128 * 32];   // pre-swizzled tf32 L2 weights
__device__ float g_embed_t[VV * E_PAD];          // tf32 embed, zero-padded to 320
__device__ float g_h1[2][BB * HH];
__device__ float g_h2[2][BB * HH];
__device__ float g_h1t[2][BB * HH];              // tf32 copies (MMA A input)
__device__ float g_h2t[2][BB * HH];
__device__ float g_c1[BB * HH];
__device__ float g_c2[BB * HH];
__device__ float g_bc1[4 * HH];                  // bih + bhh combined
__device__ float g_bc2[4 * HH];

__device__ __forceinline__ unsigned cvt_tf32(float x) {
    unsigned r;
    asm("cvt.rna.tf32.f32 %0, %1;" : "=r"(r) : "f"(x));
    return r;
}

__device__ __forceinline__ void cp16(unsigned dst, const void* src) {
    asm volatile("cp.async.cg.shared.global [%0], [%1], 16;"
                 :: "r"(dst), "l"(src));
}

__global__ void init_states_kernel() {
    int i = blockIdx.x * blockDim.x + threadIdx.x;
    if (i < BB * HH) {
        g_h1[0][i] = 0.f; g_h2[0][i] = 0.f;
        g_h1t[0][i] = 0.f; g_h2t[0][i] = 0.f;
        g_c1[i] = 0.f; g_c2[i] = 0.f;
    }
}

__global__ void conv_bias_kernel(const float* __restrict__ bih1, const float* __restrict__ bhh1,
                                 const float* __restrict__ bih2, const float* __restrict__ bhh2) {
    int i = blockIdx.x * blockDim.x + threadIdx.x;
    if (i < 4 * HH) {
        g_bc1[i] = bih1[i] + bhh1[i];
        g_bc2[i] = bih2[i] + bhh2[i];
    }
}

__global__ void conv_embed_kernel(const float* __restrict__ embed) {
    int i = blockIdx.x * 256 + threadIdx.x;   // < VV * E_PAD (exact)
    int v = i / E_PAD, k = i % E_PAD;
    float val = (k < EE) ? embed[(size_t)v * EE + k] : 0.f;
    g_embed_t[i] = __uint_as_float(cvt_tf32(val));
}

// Build per-(n-group, k-tile) smem-image weight tiles, tf32-rounded,
// with the k4 ^ (n&7) swizzle pre-applied.
// dst word d within a 4096-word tile: n = d>>5, slot s = (d&31)>>2, eo = d&3
// holds k_in_tile = ((s ^ (n&7)) << 2) + eo.
__global__ void conv_w_kernel(float* __restrict__ dst,
                              const float* __restrict__ Wih,
                              const float* __restrict__ Whh,
                              int Kin, int Kpad, int NT) {
    int e = blockIdx.x * 256 + threadIdx.x;   // < NB*NT*4096 (exact)
    int d = e & 4095;
    int tile = (e >> 12) % NT;
    int nb = (e >> 12) / NT;
    int n = d >> 5, w = d & 31, s = w >> 2, eo = w & 3;
    int kt = ((s ^ (n & 7)) << 2) + eo;
    int kg = tile * 32 + kt;
    int oct = n >> 3, u = n & 7, gate = oct & 3, uo = oct >> 2;
    int r = gate * HH + nb * 32 + uo * 8 + u;
    float v;
    if (kg < Kpad) v = (kg < Kin) ? Wih[(size_t)r * Kin + kg] : 0.f;
    else           v = Whh[(size_t)r * HH + (kg - Kpad)];
    dst[e] = __uint_as_float(cvt_tf32(v));
}

// Fused tf32-MMA GEMM + LSTM cell, one layer, one timestep.
// grid = 64: nb = blockIdx & 31 (128 gate-cols = 32 units x 4 gates),
//            mb = blockIdx >> 5 (32 batch rows).
// 256 threads = 8 warps: wm = warp>>2 (m-half of 16), wn = warp&3 (32 cols).
// Warp's 4 n-subtiles (8 cols each) = gates i/f/g/o of units u0+8*wn+(0..7)
// -> thread-local LSTM epilogue. Operands arrive pre-converted tf32; zero CVT
// in the hot loop. 8-stage cp.async ring.
__global__ __launch_bounds__(256) void lstm_step_mma(
    const float* __restrict__ Wpre, int NT, int ntile0,
    const float* __restrict__ A0, int strideA0, int gather,
    const int*   __restrict__ questions,
    const int*   __restrict__ qlen,
    const float* __restrict__ A1,      // hprev tf32 (recurrent phase A)
    const float* __restrict__ hprev,   // hprev fp32 (epilogue freeze)
    const float* __restrict__ bc,      // combined bias [4H]
    float* __restrict__ cbuf,
    float* __restrict__ hout,
    float* __restrict__ houtT,
    int t)
{
    extern __shared__ __align__(16) float smem_dyn[];
    __shared__ int qidxS[32];

    const int tid  = threadIdx.x;
    const int lane = tid & 31;
    const int warp = tid >> 5;
    const int nb   = blockIdx.x & 31;
    const int mb   = blockIdx.x >> 5;
    const int u0   = nb * 32;

    if (gather && tid < 32) qidxS[tid] = questions[(mb * 32 + tid) * TT + t];
    __syncthreads();

    const unsigned smem_base = (unsigned)__cvta_generic_to_shared(smem_dyn);

    float acc[4][4];
#pragma unroll
    for (int j = 0; j < 4; ++j)
#pragma unroll
        for (int r = 0; r < 4; ++r) acc[j][r] = 0.f;

    const int am = tid >> 3;          // A-load row 0..31
    const int ak4 = tid & 7;
    const unsigned a_dst_off = (unsigned)((am * 8 + (ak4 ^ (am & 7))) * 16);

    auto issue_tile = [&](int tt, int stage) {
        const unsigned ab = smem_base + (unsigned)(stage * STAGE_BYTES);
        const unsigned wb = ab + A_TILE_WORDS * 4;
        // W tile: contiguous pre-swizzled image, 4 float4s per thread
        const float4* wsrc = (const float4*)(Wpre + ((size_t)nb * NT + tt) * (size_t)W_TILE_WORDS);
#pragma unroll
        for (int j = 0; j < 4; ++j) {
            int i4 = tid + j * 256;
            cp16(wb + (unsigned)(i4 * 16), wsrc + i4);
        }
        // A tile: 1 float4 per thread
        const float* srcA;
        if (tt < ntile0) {
            int row = gather ? qidxS[am] : (mb * 32 + am);
            srcA = A0 + (size_t)row * strideA0 + tt * 32 + ak4 * 4;
        } else {
            srcA = A1 + (size_t)(mb * 32 + am) * HH + (tt - ntile0) * 32 + ak4 * 4;
        }
        cp16(ab + a_dst_off, srcA);
    };

#pragma unroll
    for (int p = 0; p < NSTAGE - 1; ++p) {
        issue_tile(p, p);
        asm volatile("cp.async.commit_group;");
    }

    const int g  = lane >> 2;   // 0..7
    const int th = lane & 3;    // 0..3
    const int wm = warp >> 2;
    const int wn = warp & 3;
    const int mrow = wm * 16 + g;

    for (int tt = 0; tt < NT; ++tt) {
        asm volatile("cp.async.wait_group %0;" :: "n"(NSTAGE - 2));
        __syncthreads();

        const int stage = tt & (NSTAGE - 1);
        const unsigned* __restrict__ A =
            (const unsigned*)smem_dyn + stage * STAGE_WORDS;
        const unsigned* __restrict__ W = A + A_TILE_WORDS;

#pragma unroll
        for (int c = 0; c < 4; ++c) {          // k-chunk of 8
            const int xr0 = ((2 * c)     ^ g) << 2;
            const int xr1 = ((2 * c + 1) ^ g) << 2;
            unsigned a0 = A[ mrow      * 32 + xr0 + th];
            unsigned a1 = A[(mrow + 8) * 32 + xr0 + th];
            unsigned a2 = A[ mrow      * 32 + xr1 + th];
            unsigned a3 = A[(mrow + 8) * 32 + xr1 + th];
#pragma unroll
            for (int j = 0; j < 4; ++j) {      // n-subtile == gate j
                const int n = 32 * wn + 8 * j + g;
                unsigned b0 = W[n * 32 + xr0 + th];
                unsigned b1 = W[n * 32 + xr1 + th];
                asm volatile(
                    "mma.sync.aligned.m16n8k8.row.col.f32.tf32.tf32.f32 "
                    "{%0,%1,%2,%3}, {%4,%5,%6,%7}, {%8,%9}, {%0,%1,%2,%3};"
                    : "+f"(acc[j][0]), "+f"(acc[j][1]),
                      "+f"(acc[j][2]), "+f"(acc[j][3])
                    : "r"(a0), "r"(a1), "r"(a2), "r"(a3), "r"(b0), "r"(b1));
            }
        }

        int nt = tt + NSTAGE - 1;
        if (nt < NT) issue_tile(nt, nt & (NSTAGE - 1));
        asm volatile("cp.async.commit_group;");
    }

    // ---- thread-local LSTM cell epilogue ----
#pragma unroll
    for (int r = 0; r < 4; ++r) {
        int b  = mb * 32 + wm * 16 + g + ((r >> 1) << 3);
        int gu = u0 + 8 * wn + 2 * th + (r & 1);
        float gi = acc[0][r] + bc[gu];
        float gf = acc[1][r] + bc[gu + HH];
        float gg = acc[2][r] + bc[gu + 2 * HH];
        float go = acc[3][r] + bc[gu + 3 * HH];
        int idx = b * HH + gu;
        float c_old = cbuf[idx];
        float h_old = hprev[idx];
        float si = 1.f / (1.f + expf(-gi));
        float sf = 1.f / (1.f + expf(-gf));
        float so = 1.f / (1.f + expf(-go));
        float tg = tanhf(gg);
        float cn = sf * c_old + si * tg;
        float hn = so * tanhf(cn);
        bool active = (t < qlen[b]);
        float cw = active ? cn : c_old;
        float hw = active ? hn : h_old;
        cbuf[idx]  = cw;
        hout[idx]  = hw;
        houtT[idx] = __uint_as_float(cvt_tf32(hw));
    }
}

// Output: E_q [B,1024,28,28] = tiled h2, then h1, h2, c1, c2 each [B,1,H].
__global__ void write_output_kernel(
    float* __restrict__ out,
    const float* __restrict__ h1,
    const float* __restrict__ h2,
    const float* __restrict__ c1,
    const float* __restrict__ c2)
{
    const unsigned n0q = (unsigned)BB * HH * 784u / 4u;
    const unsigned sq  = (unsigned)BB * HH / 4u;
    unsigned idx = blockIdx.x * blockDim.x + threadIdx.x;
    unsigned totq = n0q + 4u * sq;
    if (idx >= totq) return;
    float4* out4 = (float4*)out;
    if (idx < n0q) {
        unsigned bh = idx / 196u;
        float v = h2[bh];
        out4[idx] = make_float4(v, v, v, v);
    } else {
        unsigned r = idx - n0q;
        unsigned sec = r / sq;
        unsigned off = r % sq;
        const float* src = (sec == 0) ? h1 : (sec == 1) ? h2 : (sec == 2) ? c1 : c2;
        out4[idx] = ((const float4*)src)[off];
    }
}

extern "C" void kernel_launch(void* const* d_in, const int* in_sizes, int n_in,
                              void* d_out, int out_size) {
    const int*   questions = (const int*)d_in[0];
    const int*   qlen      = (const int*)d_in[1];
    const float* embed     = (const float*)d_in[2];
    const float* Wih1      = (const float*)d_in[3];
    const float* Whh1      = (const float*)d_in[4];
    const float* bih1      = (const float*)d_in[5];
    const float* bhh1      = (const float*)d_in[6];
    const float* Wih2      = (const float*)d_in[7];
    const float* Whh2      = (const float*)d_in[8];
    const float* bih2      = (const float*)d_in[9];
    const float* bhh2      = (const float*)d_in[10];

    void* p;
    cudaGetSymbolAddress(&p, g_h1);  float (*h1b)[BB*HH]  = (float(*)[BB*HH])p;
    cudaGetSymbolAddress(&p, g_h2);  float (*h2b)[BB*HH]  = (float(*)[BB*HH])p;
    cudaGetSymbolAddress(&p, g_h1t); float (*h1tb)[BB*HH] = (float(*)[BB*HH])p;
    cudaGetSymbolAddress(&p, g_h2t); float (*h2tb)[BB*HH] = (float(*)[BB*HH])p;
    cudaGetSymbolAddress(&p, g_c1);  float* c1p = (float*)p;
    cudaGetSymbolAddress(&p, g_c2);  float* c2p = (float*)p;
    cudaGetSymbolAddress(&p, g_w1pre); float* w1p = (float*)p;
    cudaGetSymbolAddress(&p, g_w2pre); float* w2p = (float*)p;
    cudaGetSymbolAddress(&p, g_embed_t); float* ep = (float*)p;
    cudaGetSymbolAddress(&p, g_bc1); float* bc1p = (float*)p;
    cudaGetSymbolAddress(&p, g_bc2); float* bc2p = (float*)p;

    cudaFuncSetAttribute(lstm_step_mma,
                         cudaFuncAttributeMaxDynamicSharedMemorySize, SMEM_DYN);

    // ---- per-replay preprocessing ----
    conv_bias_kernel<<<(4 * HH + 255) / 256, 256>>>(bih1, bhh1, bih2, bhh2);
    conv_embed_kernel<<<VV * E_PAD / 256, 256>>>(embed);
    conv_w_kernel<<<NB * NT1 * 4096 / 256, 256>>>(w1p, Wih1, Whh1, EE, E_PAD, NT1);
    conv_w_kernel<<<NB * NT2 * 4096 / 256, 256>>>(w2p, Wih2, Whh2, HH, HH, NT2);
    init_states_kernel<<<(BB * HH + 255) / 256, 256>>>();

    for (int t = 0; t < TT; ++t) {
        int rd = t & 1, wr = (t + 1) & 1;
        // Layer 1: A0 = padded tf32 embed (gathered), A1 = h1t prev
        lstm_step_mma<<<64, 256, SMEM_DYN>>>(
            w1p, NT1, NTILE0_1,
            ep, E_PAD, 1, questions, qlen,
            h1tb[rd], h1b[rd], bc1p,
            c1p, h1b[wr], h1tb[wr], t);
        // Layer 2: A0 = new h1 tf32, A1 = h2t prev
        lstm_step_mma<<<64, 256, SMEM_DYN>>>(
            w2p, NT2, NTILE0_2,
            h1tb[wr], HH, 0, questions, qlen,
            h2tb[rd], h2b[rd], bc2p,
            c2p, h2b[wr], h2tb[wr], t);
    }

    // final states live in buffer index (T % 2) == 0
    unsigned totq = (unsigned)BB * HH * 784u / 4u + (unsigned)BB * HH;
    write_output_kernel<<<(totq + 255) / 256, 256>>>(
        (float*)d_out, h1b[0], h2b[0], c1p, c2p);
}

// round 8
// speedup vs baseline: 1.3737x; 1.3737x over previous
#include <cuda_runtime.h>
#include <math.h>

#define BB 64
#define TT 32
#define EE 300
#define HH 1024
#define VV 10000

#define E_PAD 320
#define NT1   ((E_PAD + HH) / 32)   // 42 k-tiles, layer 1
#define NTILE0_1 (E_PAD / 32)       // 10
#define NT2   ((HH + HH) / 32)      // 64 k-tiles, layer 2
#define NTILE0_2 (HH / 32)          // 32
#define NBLK 128                     // n-groups of 32 gate-cols (8 units x 4 gates)

#define NPAIR 6                      // ring of 6 pairs = 12 tile stages
#define A_TILE_WORDS (64 * 32)       // 2048
#define W_TILE_WORDS (32 * 32)       // 1024
#define STAGE_WORDS  (A_TILE_WORDS + W_TILE_WORDS)   // 3072 (12KB)
#define STAGE_BYTES  (STAGE_WORDS * 4)
#define SMEM_DYN     (2 * NPAIR * STAGE_BYTES)       // 147456

// ---- persistent device scratch (no allocation allowed) ----
__device__ float g_w1pre[NBLK * NT1 * W_TILE_WORDS];  // pre-swizzled tf32 L1 W
__device__ float g_w2pre[NBLK * NT2 * W_TILE_WORDS];  // pre-swizzled tf32 L2 W
__device__ float g_embed_t[VV * E_PAD];               // tf32 embed, padded
__device__ float g_h1[2][BB * HH];
__device__ float g_h2[2][BB * HH];
__device__ float g_h1t[2][BB * HH];                   // tf32 copies (MMA A)
__device__ float g_h2t[2][BB * HH];
__device__ float g_c1[BB * HH];
__device__ float g_c2[BB * HH];
__device__ float g_bc1[4 * HH];
__device__ float g_bc2[4 * HH];

__device__ __forceinline__ unsigned cvt_tf32(float x) {
    unsigned r;
    asm("cvt.rna.tf32.f32 %0, %1;" : "=r"(r) : "f"(x));
    return r;
}

__device__ __forceinline__ void cp16(unsigned dst, const void* src) {
    asm volatile("cp.async.cg.shared.global [%0], [%1], 16;"
                 :: "r"(dst), "l"(src));
}

__global__ void init_states_kernel() {
    int i = blockIdx.x * blockDim.x + threadIdx.x;
    if (i < BB * HH) {
        g_h1[0][i] = 0.f; g_h2[0][i] = 0.f;
        g_h1t[0][i] = 0.f; g_h2t[0][i] = 0.f;
        g_c1[i] = 0.f; g_c2[i] = 0.f;
    }
}

__global__ void conv_bias_kernel(const float* __restrict__ bih1, const float* __restrict__ bhh1,
                                 const float* __restrict__ bih2, const float* __restrict__ bhh2) {
    int i = blockIdx.x * blockDim.x + threadIdx.x;
    if (i < 4 * HH) {
        g_bc1[i] = bih1[i] + bhh1[i];
        g_bc2[i] = bih2[i] + bhh2[i];
    }
}

__global__ void conv_embed_kernel(const float* __restrict__ embed) {
    int i = blockIdx.x * 256 + threadIdx.x;   // < VV * E_PAD (exact)
    int v = i / E_PAD, k = i % E_PAD;
    float val = (k < EE) ? embed[(size_t)v * EE + k] : 0.f;
    g_embed_t[i] = __uint_as_float(cvt_tf32(val));
}

// Pre-swizzled tf32 weight tiles, one 1024-word image per (n-group, k-tile).
// Word d in tile: n = d>>5 (0..31 col), s = (d&31)>>2, eo = d&3 holds
// k_in_tile = ((s ^ (n&7)) << 2) + eo. Col n: gate = n>>3, unit = nb*8 + (n&7).
__global__ void conv_w_kernel(float* __restrict__ dst,
                              const float* __restrict__ Wih,
                              const float* __restrict__ Whh,
                              int Kin, int Kpad, int NT) {
    int e = blockIdx.x * 256 + threadIdx.x;   // < NBLK*NT*1024 (exact)
    int d = e & 1023;
    int tile = (e >> 10) % NT;
    int nb = (e >> 10) / NT;
    int n = d >> 5, w = d & 31, s = w >> 2, eo = w & 3;
    int kt = ((s ^ (n & 7)) << 2) + eo;
    int kg = tile * 32 + kt;
    int r = (n >> 3) * HH + nb * 8 + (n & 7);
    float v;
    if (kg < Kpad) v = (kg < Kin) ? Wih[(size_t)r * Kin + kg] : 0.f;
    else           v = Whh[(size_t)r * HH + (kg - Kpad)];
    dst[e] = __uint_as_float(cvt_tf32(v));
}

// Fused tf32-MMA GEMM + LSTM cell, one layer, one timestep.
// grid = 128: u0 = blockIdx*8, block tile M=64 (all batch) x N=32 gate-cols.
// 256 threads = 8 warps: wk = warp>>2 (K-split half), wm = warp&3 (16 rows).
// Half wk accumulates k-tiles of parity wk; partials summed via smem at end.
// Warp n-subtiles = gates i/f/g/o of same 8 units -> thread-local epilogue.
// 12-stage (6-pair) cp.async ring, one __syncthreads per tile-pair.
__global__ __launch_bounds__(256) void lstm_step_mma(
    const float* __restrict__ Wpre, int NT, int ntile0,
    const float* __restrict__ A0, int strideA0, int gather,
    const int*   __restrict__ questions,
    const int*   __restrict__ qlen,
    const float* __restrict__ A1,      // hprev tf32 (recurrent phase A)
    const float* __restrict__ hprev,   // hprev fp32 (epilogue freeze)
    const float* __restrict__ bc,      // combined bias [4H]
    float* __restrict__ cbuf,
    float* __restrict__ hout,
    float* __restrict__ houtT,
    int t)
{
    extern __shared__ __align__(16) float smem_dyn[];
    __shared__ int   qidxS[BB];
    __shared__ float redS[4][32][17];   // padded: k-split partial sums

    const int tid  = threadIdx.x;
    const int lane = tid & 31;
    const int warp = tid >> 5;
    const int u0   = blockIdx.x * 8;

    if (gather && tid < BB) qidxS[tid] = questions[tid * TT + t];
    __syncthreads();

    const unsigned smem_base = (unsigned)__cvta_generic_to_shared(smem_dyn);

    float acc[4][4];
#pragma unroll
    for (int j = 0; j < 4; ++j)
#pragma unroll
        for (int r = 0; r < 4; ++r) acc[j][r] = 0.f;

    const int am  = tid >> 3;     // A-load row for idx<256 (rows 0..31)
    const int ak4 = tid & 7;

    auto issue_tile = [&](int tt, int stage) {
        const unsigned ab = smem_base + (unsigned)(stage * STAGE_BYTES);
        const unsigned wb = ab + A_TILE_WORDS * 4;
        // W tile: contiguous pre-swizzled image, 1 float4 per thread
        const float4* wsrc = (const float4*)(Wpre + ((size_t)blockIdx.x * NT + tt) * (size_t)W_TILE_WORDS);
        cp16(wb + (unsigned)(tid * 16), wsrc + tid);
        // A tile: 512 float4s, 2 per thread
#pragma unroll
        for (int j = 0; j < 2; ++j) {
            int idx = tid + j * 256;
            int m = idx >> 3, k4 = idx & 7;
            const float* srcA;
            if (tt < ntile0) {
                int row = gather ? qidxS[m] : m;
                srcA = A0 + (size_t)row * strideA0 + tt * 32 + k4 * 4;
            } else {
                srcA = A1 + (size_t)m * HH + (tt - ntile0) * 32 + k4 * 4;
            }
            cp16(ab + (unsigned)((m * 8 + (k4 ^ (m & 7))) * 16), srcA);
        }
    };

    auto issue_pair = [&](int p) {
        int s2 = (p % NPAIR) * 2;
        issue_tile(2 * p,     s2);
        issue_tile(2 * p + 1, s2 + 1);
    };

    const int npairs = NT >> 1;   // NT always even (42 or 64)

    // Prologue: 5 pairs in flight (npairs >= 21 always)
#pragma unroll
    for (int p = 0; p < NPAIR - 1; ++p) {
        issue_pair(p);
        asm volatile("cp.async.commit_group;");
    }

    const int g  = lane >> 2;   // 0..7
    const int th = lane & 3;    // 0..3
    const int wk = warp >> 2;   // k-split half
    const int wm = warp & 3;
    const int mrow = wm * 16 + g;

    for (int p = 0; p < npairs; ++p) {
        asm volatile("cp.async.wait_group %0;" :: "n"(NPAIR - 2));
        __syncthreads();

        // this warp-half computes tile 2p + wk from its stage
        const int stage = (p % NPAIR) * 2 + wk;
        const unsigned* __restrict__ A =
            (const unsigned*)smem_dyn + stage * STAGE_WORDS;
        const unsigned* __restrict__ W = A + A_TILE_WORDS;

#pragma unroll
        for (int c = 0; c < 4; ++c) {          // k-chunk of 8
            const int xr0 = ((2 * c)     ^ g) << 2;
            const int xr1 = ((2 * c + 1) ^ g) << 2;
            unsigned a0 = A[ mrow      * 32 + xr0 + th];
            unsigned a1 = A[(mrow + 8) * 32 + xr0 + th];
            unsigned a2 = A[ mrow      * 32 + xr1 + th];
            unsigned a3 = A[(mrow + 8) * 32 + xr1 + th];
#pragma unroll
            for (int j = 0; j < 4; ++j) {      // n-subtile == gate j
                const int n = 8 * j + g;
                unsigned b0 = W[n * 32 + xr0 + th];
                unsigned b1 = W[n * 32 + xr1 + th];
                asm volatile(
                    "mma.sync.aligned.m16n8k8.row.col.f32.tf32.tf32.f32 "
                    "{%0,%1,%2,%3}, {%4,%5,%6,%7}, {%8,%9}, {%0,%1,%2,%3};"
                    : "+f"(acc[j][0]), "+f"(acc[j][1]),
                      "+f"(acc[j][2]), "+f"(acc[j][3])
                    : "r"(a0), "r"(a1), "r"(a2), "r"(a3), "r"(b0), "r"(b1));
            }
        }

        int np = p + NPAIR - 1;
        if (np < npairs) issue_pair(np);
        asm volatile("cp.async.commit_group;");   // always commit (FIFO arithmetic)
    }

    // ---- K-split reduction + thread-local LSTM cell epilogue ----
    if (wk == 1) {
#pragma unroll
        for (int j = 0; j < 4; ++j)
#pragma unroll
            for (int r = 0; r < 4; ++r)
                redS[wm][lane][j * 4 + r] = acc[j][r];
    }
    __syncthreads();
    if (wk == 0) {
#pragma unroll
        for (int j = 0; j < 4; ++j)
#pragma unroll
            for (int r = 0; r < 4; ++r)
                acc[j][r] += redS[wm][lane][j * 4 + r];

#pragma unroll
        for (int r = 0; r < 4; ++r) {
            int b  = wm * 16 + g + ((r >> 1) << 3);
            int gu = u0 + 2 * th + (r & 1);
            float gi = acc[0][r] + bc[gu];
            float gf = acc[1][r] + bc[gu + HH];
            float gg = acc[2][r] + bc[gu + 2 * HH];
            float go = acc[3][r] + bc[gu + 3 * HH];
            int idx = b * HH + gu;
            float c_old = cbuf[idx];
            float h_old = hprev[idx];
            float si = 1.f / (1.f + expf(-gi));
            float sf = 1.f / (1.f + expf(-gf));
            float so = 1.f / (1.f + expf(-go));
            float tg = tanhf(gg);
            float cn = sf * c_old + si * tg;
            float hn = so * tanhf(cn);
            bool active = (t < qlen[b]);
            float cw = active ? cn : c_old;
            float hw = active ? hn : h_old;
            cbuf[idx]  = cw;
            hout[idx]  = hw;
            houtT[idx] = __uint_as_float(cvt_tf32(hw));
        }
    }
}

// Output: E_q [B,1024,28,28] = tiled h2, then h1, h2, c1, c2 each [B,1,H].
__global__ void write_output_kernel(
    float* __restrict__ out,
    const float* __restrict__ h1,
    const float* __restrict__ h2,
    const float* __restrict__ c1,
    const float* __restrict__ c2)
{
    const unsigned n0q = (unsigned)BB * HH * 784u / 4u;
    const unsigned sq  = (unsigned)BB * HH / 4u;
    unsigned idx = blockIdx.x * blockDim.x + threadIdx.x;
    unsigned totq = n0q + 4u * sq;
    if (idx >= totq) return;
    float4* out4 = (float4*)out;
    if (idx < n0q) {
        unsigned bh = idx / 196u;
        float v = h2[bh];
        out4[idx] = make_float4(v, v, v, v);
    } else {
        unsigned r = idx - n0q;
        unsigned sec = r / sq;
        unsigned off = r % sq;
        const float* src = (sec == 0) ? h1 : (sec == 1) ? h2 : (sec == 2) ? c1 : c2;
        out4[idx] = ((const float4*)src)[off];
    }
}

extern "C" void kernel_launch(void* const* d_in, const int* in_sizes, int n_in,
                              void* d_out, int out_size) {
    const int*   questions = (const int*)d_in[0];
    const int*   qlen      = (const int*)d_in[1];
    const float* embed     = (const float*)d_in[2];
    const float* Wih1      = (const float*)d_in[3];
    const float* Whh1      = (const float*)d_in[4];
    const float* bih1      = (const float*)d_in[5];
    const float* bhh1      = (const float*)d_in[6];
    const float* Wih2      = (const float*)d_in[7];
    const float* Whh2      = (const float*)d_in[8];
    const float* bih2      = (const float*)d_in[9];
    const float* bhh2      = (const float*)d_in[10];

    void* p;
    cudaGetSymbolAddress(&p, g_h1);  float (*h1b)[BB*HH]  = (float(*)[BB*HH])p;
    cudaGetSymbolAddress(&p, g_h2);  float (*h2b)[BB*HH]  = (float(*)[BB*HH])p;
    cudaGetSymbolAddress(&p, g_h1t); float (*h1tb)[BB*HH] = (float(*)[BB*HH])p;
    cudaGetSymbolAddress(&p, g_h2t); float (*h2tb)[BB*HH] = (float(*)[BB*HH])p;
    cudaGetSymbolAddress(&p, g_c1);  float* c1p = (float*)p;
    cudaGetSymbolAddress(&p, g_c2);  float* c2p = (float*)p;
    cudaGetSymbolAddress(&p, g_w1pre); float* w1p = (float*)p;
    cudaGetSymbolAddress(&p, g_w2pre); float* w2p = (float*)p;
    cudaGetSymbolAddress(&p, g_embed_t); float* ep = (float*)p;
    cudaGetSymbolAddress(&p, g_bc1); float* bc1p = (float*)p;
    cudaGetSymbolAddress(&p, g_bc2); float* bc2p = (float*)p;

    cudaFuncSetAttribute(lstm_step_mma,
                         cudaFuncAttributeMaxDynamicSharedMemorySize, SMEM_DYN);

    // ---- per-replay preprocessing ----
    conv_bias_kernel<<<(4 * HH + 255) / 256, 256>>>(bih1, bhh1, bih2, bhh2);
    conv_embed_kernel<<<VV * E_PAD / 256, 256>>>(embed);
    conv_w_kernel<<<NBLK * NT1 * W_TILE_WORDS / 256, 256>>>(w1p, Wih1, Whh1, EE, E_PAD, NT1);
    conv_w_kernel<<<NBLK * NT2 * W_TILE_WORDS / 256, 256>>>(w2p, Wih2, Whh2, HH, HH, NT2);
    init_states_kernel<<<(BB * HH + 255) / 256, 256>>>();

    for (int t = 0; t < TT; ++t) {
        int rd = t & 1, wr = (t + 1) & 1;
        // Layer 1: A0 = padded tf32 embed (gathered), A1 = h1t prev
        lstm_step_mma<<<NBLK, 256, SMEM_DYN>>>(
            w1p, NT1, NTILE0_1,
            ep, E_PAD, 1, questions, qlen,
            h1tb[rd], h1b[rd], bc1p,
            c1p, h1b[wr], h1tb[wr], t);
        // Layer 2: A0 = new h1 tf32, A1 = h2t prev
        lstm_step_mma<<<NBLK, 256, SMEM_DYN>>>(
            w2p, NT2, NTILE0_2,
            h1tb[wr], HH, 0, questions, qlen,
            h2tb[rd], h2b[rd], bc2p,
            c2p, h2b[wr], h2tb[wr], t);
    }

    // final states live in buffer index (T % 2) == 0
    unsigned totq = (unsigned)BB * HH * 784u / 4u + (unsigned)BB * HH;
    write_output_kernel<<<(totq + 255) / 256, 256>>>(
        (float*)d_out, h1b[0], h2b[0], c1p, c2p);
}

// round 9
// speedup vs baseline: 1.6992x; 1.2370x over previous
#include <cuda_runtime.h>
#include <math.h>

#define BB 64
#define TT 32
#define EE 300
#define HH 1024
#define VV 10000

#define E_PAD 320
#define NT1   ((E_PAD + HH) / 32)   // 42 k-tiles, layer 1
#define NTILE0_1 (E_PAD / 32)       // 10
#define NT2   ((HH + HH) / 32)      // 64 k-tiles, layer 2
#define NTILE0_2 (HH / 32)          // 32
#define NBLK 128                     // n-groups of 32 gate-cols per layer

#define NPAIR 4                      // ring of 4 pairs = 8 tile stages (96KB)
#define A_TILE_WORDS (64 * 32)       // 2048
#define W_TILE_WORDS (32 * 32)       // 1024
#define STAGE_WORDS  (A_TILE_WORDS + W_TILE_WORDS)   // 3072 (12KB)
#define STAGE_BYTES  (STAGE_WORDS * 4)
#define SMEM_DYN     (2 * NPAIR * STAGE_BYTES)       // 98304

// ---- persistent device scratch (no allocation allowed) ----
__device__ float g_w1pre[NBLK * NT1 * W_TILE_WORDS];  // pre-swizzled tf32 L1 W
__device__ float g_w2pre[NBLK * NT2 * W_TILE_WORDS];  // pre-swizzled tf32 L2 W
__device__ float g_embed_t[VV * E_PAD];               // tf32 embed, padded
__device__ float g_h1[2][BB * HH];
__device__ float g_h2[2][BB * HH];
__device__ float g_h1t[2][BB * HH];                   // tf32 copies (MMA A)
__device__ float g_h2t[2][BB * HH];
__device__ float g_c1[BB * HH];
__device__ float g_c2[BB * HH];
__device__ float g_bc1[4 * HH];
__device__ float g_bc2[4 * HH];

__device__ __forceinline__ unsigned cvt_tf32(float x) {
    unsigned r;
    asm("cvt.rna.tf32.f32 %0, %1;" : "=r"(r) : "f"(x));
    return r;
}

__device__ __forceinline__ void cp16(unsigned dst, const void* src) {
    asm volatile("cp.async.cg.shared.global [%0], [%1], 16;"
                 :: "r"(dst), "l"(src));
}

__global__ void init_states_kernel() {
    int i = blockIdx.x * blockDim.x + threadIdx.x;
    if (i < BB * HH) {
        g_h1[0][i] = 0.f; g_h2[0][i] = 0.f;
        g_h1t[0][i] = 0.f; g_h2t[0][i] = 0.f;
        g_c1[i] = 0.f; g_c2[i] = 0.f;
    }
}

__global__ void conv_bias_kernel(const float* __restrict__ bih1, const float* __restrict__ bhh1,
                                 const float* __restrict__ bih2, const float* __restrict__ bhh2) {
    int i = blockIdx.x * blockDim.x + threadIdx.x;
    if (i < 4 * HH) {
        g_bc1[i] = bih1[i] + bhh1[i];
        g_bc2[i] = bih2[i] + bhh2[i];
    }
}

__global__ void conv_embed_kernel(const float* __restrict__ embed) {
    int i = blockIdx.x * 256 + threadIdx.x;   // < VV * E_PAD (exact)
    int v = i / E_PAD, k = i % E_PAD;
    float val = (k < EE) ? embed[(size_t)v * EE + k] : 0.f;
    g_embed_t[i] = __uint_as_float(cvt_tf32(val));
}

// Pre-swizzled tf32 weight tiles, one 1024-word image per (n-group, k-tile).
// Word d in tile: n = d>>5 (col 0..31), s = (d&31)>>2, eo = d&3 holds
// k_in_tile = ((s ^ (n&7)) << 2) + eo. Col n: gate = n>>3, unit = nb*8 + (n&7).
__global__ void conv_w_kernel(float* __restrict__ dst,
                              const float* __restrict__ Wih,
                              const float* __restrict__ Whh,
                              int Kin, int Kpad, int NT) {
    int e = blockIdx.x * 256 + threadIdx.x;   // < NBLK*NT*1024 (exact)
    int d = e & 1023;
    int tile = (e >> 10) % NT;
    int nb = (e >> 10) / NT;
    int n = d >> 5, w = d & 31, s = w >> 2, eo = w & 3;
    int kt = ((s ^ (n & 7)) << 2) + eo;
    int kg = tile * 32 + kt;
    int r = (n >> 3) * HH + nb * 8 + (n & 7);
    float v;
    if (kg < Kpad) v = (kg < Kin) ? Wih[(size_t)r * Kin + kg] : 0.f;
    else           v = Whh[(size_t)r * HH + (kg - Kpad)];
    dst[e] = __uint_as_float(cvt_tf32(v));
}

// Merged software-pipelined step: blocks 0..127 run L2[t2], blocks 128..255
// run L1[t1] (independent: L1[t1] needs only h1[t1-1]; L2[t2] needs h1[t2]
// written last launch). Per block: M=64 x N=32 gate-cols, 8 warps with
// K-split (wk = warp>>2 accumulates k-tiles of parity wk), 8-stage cp.async
// ring, one __syncthreads per tile-pair, thread-local LSTM epilogue.
__global__ __launch_bounds__(256, 2) void lstm_merged_step(
    const int* __restrict__ questions,
    const int* __restrict__ qlen,
    int t1, int t2)
{
    extern __shared__ __align__(16) float smem_dyn[];
    __shared__ int   qidxS[BB];
    __shared__ float redS[4][32][17];

    const int tid  = threadIdx.x;
    const int lane = tid & 31;
    const int warp = tid >> 5;

    const bool isL2 = (t2 >= 0) && (blockIdx.x < NBLK);
    const int nbidx = isL2 ? blockIdx.x : (blockIdx.x - ((t2 >= 0) ? NBLK : 0));
    const int u0 = nbidx * 8;

    int t, NT, ntile0, strideA0, gather;
    const float *Wpre, *A0, *A1, *hprev, *bc;
    float *cb, *ho, *hoT;
    if (isL2) {
        t = t2; Wpre = g_w2pre; NT = NT2; ntile0 = NTILE0_2;
        A0 = g_h1t[(t2 + 1) & 1]; strideA0 = HH; gather = 0;
        A1 = g_h2t[t2 & 1]; hprev = g_h2[t2 & 1]; bc = g_bc2;
        cb = g_c2; ho = g_h2[(t2 + 1) & 1]; hoT = g_h2t[(t2 + 1) & 1];
    } else {
        t = t1; Wpre = g_w1pre; NT = NT1; ntile0 = NTILE0_1;
        A0 = g_embed_t; strideA0 = E_PAD; gather = 1;
        A1 = g_h1t[t1 & 1]; hprev = g_h1[t1 & 1]; bc = g_bc1;
        cb = g_c1; ho = g_h1[(t1 + 1) & 1]; hoT = g_h1t[(t1 + 1) & 1];
    }

    if (gather && tid < BB) qidxS[tid] = questions[tid * TT + t];
    __syncthreads();

    const unsigned smem_base = (unsigned)__cvta_generic_to_shared(smem_dyn);

    float acc[4][4];
#pragma unroll
    for (int j = 0; j < 4; ++j)
#pragma unroll
        for (int r = 0; r < 4; ++r) acc[j][r] = 0.f;

    auto issue_tile = [&](int tt, int stage) {
        const unsigned ab = smem_base + (unsigned)(stage * STAGE_BYTES);
        const unsigned wb = ab + A_TILE_WORDS * 4;
        // W tile: contiguous pre-swizzled image, 1 float4 per thread
        const float4* wsrc = (const float4*)(Wpre + ((size_t)nbidx * NT + tt) * (size_t)W_TILE_WORDS);
        cp16(wb + (unsigned)(tid * 16), wsrc + tid);
        // A tile: 512 float4s, 2 per thread
#pragma unroll
        for (int j = 0; j < 2; ++j) {
            int idx = tid + j * 256;
            int m = idx >> 3, k4 = idx & 7;
            const float* srcA;
            if (tt < ntile0) {
                int row = gather ? qidxS[m] : m;
                srcA = A0 + (size_t)row * strideA0 + tt * 32 + k4 * 4;
            } else {
                srcA = A1 + (size_t)m * HH + (tt - ntile0) * 32 + k4 * 4;
            }
            cp16(ab + (unsigned)((m * 8 + (k4 ^ (m & 7))) * 16), srcA);
        }
    };

    auto issue_pair = [&](int p) {
        int s2 = (p % NPAIR) * 2;
        issue_tile(2 * p,     s2);
        issue_tile(2 * p + 1, s2 + 1);
    };

    const int npairs = NT >> 1;   // 21 or 32

    // Prologue: NPAIR-1 pairs in flight
#pragma unroll
    for (int p = 0; p < NPAIR - 1; ++p) {
        issue_pair(p);
        asm volatile("cp.async.commit_group;");
    }

    const int g  = lane >> 2;   // 0..7
    const int th = lane & 3;    // 0..3
    const int wk = warp >> 2;   // k-split half
    const int wm = warp & 3;
    const int mrow = wm * 16 + g;

    for (int p = 0; p < npairs; ++p) {
        asm volatile("cp.async.wait_group %0;" :: "n"(NPAIR - 2));
        __syncthreads();

        const int stage = (p % NPAIR) * 2 + wk;
        const unsigned* __restrict__ A =
            (const unsigned*)smem_dyn + stage * STAGE_WORDS;
        const unsigned* __restrict__ W = A + A_TILE_WORDS;

#pragma unroll
        for (int c = 0; c < 4; ++c) {          // k-chunk of 8
            const int xr0 = ((2 * c)     ^ g) << 2;
            const int xr1 = ((2 * c + 1) ^ g) << 2;
            unsigned a0 = A[ mrow      * 32 + xr0 + th];
            unsigned a1 = A[(mrow + 8) * 32 + xr0 + th];
            unsigned a2 = A[ mrow      * 32 + xr1 + th];
            unsigned a3 = A[(mrow + 8) * 32 + xr1 + th];
#pragma unroll
            for (int j = 0; j < 4; ++j) {      // n-subtile == gate j
                const int n = 8 * j + g;
                unsigned b0 = W[n * 32 + xr0 + th];
                unsigned b1 = W[n * 32 + xr1 + th];
                asm volatile(
                    "mma.sync.aligned.m16n8k8.row.col.f32.tf32.tf32.f32 "
                    "{%0,%1,%2,%3}, {%4,%5,%6,%7}, {%8,%9}, {%0,%1,%2,%3};"
                    : "+f"(acc[j][0]), "+f"(acc[j][1]),
                      "+f"(acc[j][2]), "+f"(acc[j][3])
                    : "r"(a0), "r"(a1), "r"(a2), "r"(a3), "r"(b0), "r"(b1));
            }
        }

        int np = p + NPAIR - 1;
        if (np < npairs) issue_pair(np);
        asm volatile("cp.async.commit_group;");   // always commit (FIFO arithmetic)
    }

    // ---- K-split reduction + thread-local LSTM cell epilogue ----
    if (wk == 1) {
#pragma unroll
        for (int j = 0; j < 4; ++j)
#pragma unroll
            for (int r = 0; r < 4; ++r)
                redS[wm][lane][j * 4 + r] = acc[j][r];
    }
    __syncthreads();
    if (wk == 0) {
#pragma unroll
        for (int j = 0; j < 4; ++j)
#pragma unroll
            for (int r = 0; r < 4; ++r)
                acc[j][r] += redS[wm][lane][j * 4 + r];

#pragma unroll
        for (int r = 0; r < 4; ++r) {
            int b  = wm * 16 + g + ((r >> 1) << 3);
            int gu = u0 + 2 * th + (r & 1);
            float gi = acc[0][r] + bc[gu];
            float gf = acc[1][r] + bc[gu + HH];
            float gg = acc[2][r] + bc[gu + 2 * HH];
            float go = acc[3][r] + bc[gu + 3 * HH];
            int idx = b * HH + gu;
            float c_old = cb[idx];
            float h_old = hprev[idx];
            float si = 1.f / (1.f + expf(-gi));
            float sf = 1.f / (1.f + expf(-gf));
            float so = 1.f / (1.f + expf(-go));
            float tg = tanhf(gg);
            float cn = sf * c_old + si * tg;
            float hn = so * tanhf(cn);
            bool active = (t < qlen[b]);
            float cw = active ? cn : c_old;
            float hw = active ? hn : h_old;
            cb[idx]  = cw;
            ho[idx]  = hw;
            hoT[idx] = __uint_as_float(cvt_tf32(hw));
        }
    }
}

// Output: E_q [B,1024,28,28] = tiled h2, then h1, h2, c1, c2 each [B,1,H].
__global__ void write_output_kernel(
    float* __restrict__ out,
    const float* __restrict__ h1,
    const float* __restrict__ h2,
    const float* __restrict__ c1,
    const float* __restrict__ c2)
{
    const unsigned n0q = (unsigned)BB * HH * 784u / 4u;
    const unsigned sq  = (unsigned)BB * HH / 4u;
    unsigned idx = blockIdx.x * blockDim.x + threadIdx.x;
    unsigned totq = n0q + 4u * sq;
    if (idx >= totq) return;
    float4* out4 = (float4*)out;
    if (idx < n0q) {
        unsigned bh = idx / 196u;
        float v = h2[bh];
        out4[idx] = make_float4(v, v, v, v);
    } else {
        unsigned r = idx - n0q;
        unsigned sec = r / sq;
        unsigned off = r % sq;
        const float* src = (sec == 0) ? h1 : (sec == 1) ? h2 : (sec == 2) ? c1 : c2;
        out4[idx] = ((const float4*)src)[off];
    }
}

extern "C" void kernel_launch(void* const* d_in, const int* in_sizes, int n_in,
                              void* d_out, int out_size) {
    const int*   questions = (const int*)d_in[0];
    const int*   qlen      = (const int*)d_in[1];
    const float* embed     = (const float*)d_in[2];
    const float* Wih1      = (const float*)d_in[3];
    const float* Whh1      = (const float*)d_in[4];
    const float* bih1      = (const float*)d_in[5];
    const float* bhh1      = (const float*)d_in[6];
    const float* Wih2      = (const float*)d_in[7];
    const float* Whh2      = (const float*)d_in[8];
    const float* bih2      = (const float*)d_in[9];
    const float* bhh2      = (const float*)d_in[10];

    void* p;
    cudaGetSymbolAddress(&p, g_h1);  float (*h1b)[BB*HH]  = (float(*)[BB*HH])p;
    cudaGetSymbolAddress(&p, g_h2);  float (*h2b)[BB*HH]  = (float(*)[BB*HH])p;
    cudaGetSymbolAddress(&p, g_c1);  float* c1p = (float*)p;
    cudaGetSymbolAddress(&p, g_c2);  float* c2p = (float*)p;
    cudaGetSymbolAddress(&p, g_w1pre); float* w1p = (float*)p;
    cudaGetSymbolAddress(&p, g_w2pre); float* w2p = (float*)p;

    cudaFuncSetAttribute(lstm_merged_step,
                         cudaFuncAttributeMaxDynamicSharedMemorySize, SMEM_DYN);

    // ---- per-replay preprocessing ----
    conv_bias_kernel<<<(4 * HH + 255) / 256, 256>>>(bih1, bhh1, bih2, bhh2);
    conv_embed_kernel<<<VV * E_PAD / 256, 256>>>(embed);
    conv_w_kernel<<<NBLK * NT1 * W_TILE_WORDS / 256, 256>>>(w1p, Wih1, Whh1, EE, E_PAD, NT1);
    conv_w_kernel<<<NBLK * NT2 * W_TILE_WORDS / 256, 256>>>(w2p, Wih2, Whh2, HH, HH, NT2);
    init_states_kernel<<<(BB * HH + 255) / 256, 256>>>();

    // ---- software-pipelined timestep chain ----
    // K_0: L1[0] alone; K_i (i=1..31): {L2[i-1], L1[i]}; K_32: L2[31] alone.
    lstm_merged_step<<<NBLK, 256, SMEM_DYN>>>(questions, qlen, 0, -1);
    for (int i = 1; i < TT; ++i)
        lstm_merged_step<<<2 * NBLK, 256, SMEM_DYN>>>(questions, qlen, i, i - 1);
    lstm_merged_step<<<NBLK, 256, SMEM_DYN>>>(questions, qlen, -1, TT - 1);

    // final states live in buffer index (T % 2) == 0
    unsigned totq = (unsigned)BB * HH * 784u / 4u + (unsigned)BB * HH;
    write_output_kernel<<<(totq + 255) / 256, 256>>>(
        (float*)d_out, h1b[0], h2b[0], c1p, c2p);
}